// round 2
// baseline (speedup 1.0000x reference)
#include <cuda_runtime.h>
#include <math.h>

// Problem constants
#define BB 8
#define SS 2048
#define DD 512
#define MFULL (BB * SS)          // 16384
#define INV_T (1.0f / 22.627416997969522f)
#define LN_EPS 1e-5f

// ---------------------------------------------------------------------------
// Scratch (device globals; no allocations allowed)
// ---------------------------------------------------------------------------
__device__ float g_h1[MFULL * DD];
__device__ float g_h2[MFULL * DD];
__device__ float g_dq[MFULL * DD];
__device__ float g_dk[MFULL * DD];
__device__ int   g_mask_is_i32;

// ---------------------------------------------------------------------------
// Mask dtype detector: if mask stored as int32 (little-endian 0/1), every byte
// at position %4 != 0 is zero. If bool/uint8, ~50% of those bytes are 1.
// ---------------------------------------------------------------------------
__global__ void detect_mask_kernel(const unsigned char* __restrict__ mb) {
    __shared__ int any;
    if (threadIdx.x == 0) any = 0;
    __syncthreads();
    for (int i = threadIdx.x; i < 4096; i += blockDim.x) {
        if ((i & 3) && mb[i]) atomicOr(&any, 1);
    }
    __syncthreads();
    if (threadIdx.x == 0) g_mask_is_i32 = any ? 0 : 1;
}

// ---------------------------------------------------------------------------
// Block reductions (work for 128 or 256 threads)
// ---------------------------------------------------------------------------
__device__ __forceinline__ float blockReduceSum(float v, float* sh) {
    #pragma unroll
    for (int o = 16; o > 0; o >>= 1) v += __shfl_xor_sync(0xffffffffu, v, o);
    __syncthreads();
    if ((threadIdx.x & 31) == 0) sh[threadIdx.x >> 5] = v;
    __syncthreads();
    if (threadIdx.x < 32) {
        v = (threadIdx.x < (blockDim.x >> 5)) ? sh[threadIdx.x] : 0.0f;
        #pragma unroll
        for (int o = 16; o > 0; o >>= 1) v += __shfl_xor_sync(0xffffffffu, v, o);
        if (threadIdx.x == 0) sh[0] = v;
    }
    __syncthreads();
    return sh[0];
}

__device__ __forceinline__ float blockReduceMax(float v, float* sh) {
    #pragma unroll
    for (int o = 16; o > 0; o >>= 1) v = fmaxf(v, __shfl_xor_sync(0xffffffffu, v, o));
    __syncthreads();
    if ((threadIdx.x & 31) == 0) sh[threadIdx.x >> 5] = v;
    __syncthreads();
    if (threadIdx.x < 32) {
        v = (threadIdx.x < (blockDim.x >> 5)) ? sh[threadIdx.x] : -3.0e38f;
        #pragma unroll
        for (int o = 16; o > 0; o >>= 1) v = fmaxf(v, __shfl_xor_sync(0xffffffffu, v, o));
        if (threadIdx.x == 0) sh[0] = v;
    }
    __syncthreads();
    return sh[0];
}

// ---------------------------------------------------------------------------
// NN GEMM: C[m,n] = sum_k A[m,k] * B[k,n] (+bias)(+relu)
// A row-major [M,K], B row-major [K,N]. All of M,N %128==0, K %16==0.
// Tiles: 128x128x16, 256 threads, 8x8 per thread. Double-buffered smem.
// Batched via blockIdx.z with element strides sA/sB/sC.
// ---------------------------------------------------------------------------
template<bool RELU, bool HAS_BIAS>
__global__ void __launch_bounds__(256) gemm_nn(
    const float* __restrict__ Ag, const float* __restrict__ Bg,
    const float* __restrict__ bias, float* __restrict__ Cg,
    int M, int N, int K, long long sA, long long sB, long long sC)
{
    const float* A = Ag + (long long)blockIdx.z * sA;
    const float* Bm = Bg + (long long)blockIdx.z * sB;
    float* C = Cg + (long long)blockIdx.z * sC;

    __shared__ float As[2][16][128];
    __shared__ float Bs[2][16][132];   // +4 pad

    const int tid = threadIdx.x;
    const int tx = tid & 15;
    const int ty = tid >> 4;
    const int bm = blockIdx.y * 128;
    const int bn = blockIdx.x * 128;

    // load indices (fixed per thread)
    const int ar0 = tid >> 2, ac0 = (tid & 3) * 4;             // A piece 0
    const int ar1 = (tid + 256) >> 2, ac1 = ((tid + 256) & 3) * 4;
    const int br0 = tid >> 5, bc0 = (tid & 31) * 4;            // B piece 0
    const int br1 = (tid + 256) >> 5, bc1 = ((tid + 256) & 31) * 4;

    float acc[8][8];
    #pragma unroll
    for (int i = 0; i < 8; i++)
        #pragma unroll
        for (int j = 0; j < 8; j++) acc[i][j] = 0.0f;

    const int numT = K / 16;

    // prologue: tile 0 -> buffer 0
    {
        float4 a0 = *(const float4*)(A + (long long)(bm + ar0) * K + ac0);
        float4 a1 = *(const float4*)(A + (long long)(bm + ar1) * K + ac1);
        float4 b0 = *(const float4*)(Bm + (long long)br0 * N + bn + bc0);
        float4 b1 = *(const float4*)(Bm + (long long)br1 * N + bn + bc1);
        As[0][ac0 + 0][ar0] = a0.x; As[0][ac0 + 1][ar0] = a0.y;
        As[0][ac0 + 2][ar0] = a0.z; As[0][ac0 + 3][ar0] = a0.w;
        As[0][ac1 + 0][ar1] = a1.x; As[0][ac1 + 1][ar1] = a1.y;
        As[0][ac1 + 2][ar1] = a1.z; As[0][ac1 + 3][ar1] = a1.w;
        *(float4*)&Bs[0][br0][bc0] = b0;
        *(float4*)&Bs[0][br1][bc1] = b1;
    }
    __syncthreads();

    int cur = 0;
    for (int t = 0; t < numT; t++) {
        float4 na0, na1, nb0, nb1;
        const bool more = (t + 1 < numT);
        if (more) {
            const int k0 = (t + 1) * 16;
            na0 = *(const float4*)(A + (long long)(bm + ar0) * K + k0 + ac0);
            na1 = *(const float4*)(A + (long long)(bm + ar1) * K + k0 + ac1);
            nb0 = *(const float4*)(Bm + (long long)(k0 + br0) * N + bn + bc0);
            nb1 = *(const float4*)(Bm + (long long)(k0 + br1) * N + bn + bc1);
        }
        #pragma unroll
        for (int k = 0; k < 16; k++) {
            float4 a0 = *(float4*)&As[cur][k][ty * 8];
            float4 a1 = *(float4*)&As[cur][k][ty * 8 + 4];
            float4 b0 = *(float4*)&Bs[cur][k][tx * 8];
            float4 b1 = *(float4*)&Bs[cur][k][tx * 8 + 4];
            float ra[8] = {a0.x, a0.y, a0.z, a0.w, a1.x, a1.y, a1.z, a1.w};
            float rb[8] = {b0.x, b0.y, b0.z, b0.w, b1.x, b1.y, b1.z, b1.w};
            #pragma unroll
            for (int i = 0; i < 8; i++)
                #pragma unroll
                for (int j = 0; j < 8; j++) acc[i][j] = fmaf(ra[i], rb[j], acc[i][j]);
        }
        if (more) {
            const int nx = cur ^ 1;
            As[nx][ac0 + 0][ar0] = na0.x; As[nx][ac0 + 1][ar0] = na0.y;
            As[nx][ac0 + 2][ar0] = na0.z; As[nx][ac0 + 3][ar0] = na0.w;
            As[nx][ac1 + 0][ar1] = na1.x; As[nx][ac1 + 1][ar1] = na1.y;
            As[nx][ac1 + 2][ar1] = na1.z; As[nx][ac1 + 3][ar1] = na1.w;
            *(float4*)&Bs[nx][br0][bc0] = nb0;
            *(float4*)&Bs[nx][br1][bc1] = nb1;
            __syncthreads();
            cur = nx;
        }
    }

    #pragma unroll
    for (int i = 0; i < 8; i++) {
        int row = bm + ty * 8 + i;
        #pragma unroll
        for (int j4 = 0; j4 < 2; j4++) {
            int col = bn + tx * 8 + j4 * 4;
            float4 v;
            v.x = acc[i][j4 * 4 + 0];
            v.y = acc[i][j4 * 4 + 1];
            v.z = acc[i][j4 * 4 + 2];
            v.w = acc[i][j4 * 4 + 3];
            if (HAS_BIAS) {
                const float4 b = *(const float4*)(bias + col);
                v.x += b.x; v.y += b.y; v.z += b.z; v.w += b.w;
            }
            if (RELU) {
                v.x = fmaxf(v.x, 0.0f); v.y = fmaxf(v.y, 0.0f);
                v.z = fmaxf(v.z, 0.0f); v.w = fmaxf(v.w, 0.0f);
            }
            *(float4*)(C + (long long)row * N + col) = v;
        }
    }
}

// ---------------------------------------------------------------------------
// NT GEMM with scale + mask epilogue:
// attn[b,s,t] = mask ? -1e16 : (dq[b,s,:]·dk[b,t,:]) / T
// Per batch: M=N=2048, K=512. Double-buffered smem.
// ---------------------------------------------------------------------------
__global__ void __launch_bounds__(256) gemm_nt_mask(
    const float* __restrict__ Ag, const float* __restrict__ Bg,
    float* __restrict__ Cg, const void* __restrict__ maskp)
{
    const float* A = Ag + (long long)blockIdx.z * SS * DD;
    const float* Bm = Bg + (long long)blockIdx.z * SS * DD;
    float* C = Cg + (long long)blockIdx.z * SS * SS;

    __shared__ float As[2][16][128];
    __shared__ float Bs[2][16][128];

    const int tid = threadIdx.x;
    const int tx = tid & 15;
    const int ty = tid >> 4;
    const int bm = blockIdx.y * 128;
    const int bn = blockIdx.x * 128;

    const int r0 = tid >> 2, c0 = (tid & 3) * 4;
    const int r1 = (tid + 256) >> 2, c1 = ((tid + 256) & 3) * 4;

    float acc[8][8];
    #pragma unroll
    for (int i = 0; i < 8; i++)
        #pragma unroll
        for (int j = 0; j < 8; j++) acc[i][j] = 0.0f;

    const int numT = DD / 16;

    {
        float4 a0 = *(const float4*)(A + (long long)(bm + r0) * DD + c0);
        float4 a1 = *(const float4*)(A + (long long)(bm + r1) * DD + c1);
        float4 b0 = *(const float4*)(Bm + (long long)(bn + r0) * DD + c0);
        float4 b1 = *(const float4*)(Bm + (long long)(bn + r1) * DD + c1);
        As[0][c0 + 0][r0] = a0.x; As[0][c0 + 1][r0] = a0.y;
        As[0][c0 + 2][r0] = a0.z; As[0][c0 + 3][r0] = a0.w;
        As[0][c1 + 0][r1] = a1.x; As[0][c1 + 1][r1] = a1.y;
        As[0][c1 + 2][r1] = a1.z; As[0][c1 + 3][r1] = a1.w;
        Bs[0][c0 + 0][r0] = b0.x; Bs[0][c0 + 1][r0] = b0.y;
        Bs[0][c0 + 2][r0] = b0.z; Bs[0][c0 + 3][r0] = b0.w;
        Bs[0][c1 + 0][r1] = b1.x; Bs[0][c1 + 1][r1] = b1.y;
        Bs[0][c1 + 2][r1] = b1.z; Bs[0][c1 + 3][r1] = b1.w;
    }
    __syncthreads();

    int cur = 0;
    for (int t = 0; t < numT; t++) {
        float4 na0, na1, nb0, nb1;
        const bool more = (t + 1 < numT);
        if (more) {
            const int k0 = (t + 1) * 16;
            na0 = *(const float4*)(A + (long long)(bm + r0) * DD + k0 + c0);
            na1 = *(const float4*)(A + (long long)(bm + r1) * DD + k0 + c1);
            nb0 = *(const float4*)(Bm + (long long)(bn + r0) * DD + k0 + c0);
            nb1 = *(const float4*)(Bm + (long long)(bn + r1) * DD + k0 + c1);
        }
        #pragma unroll
        for (int k = 0; k < 16; k++) {
            float4 a0 = *(float4*)&As[cur][k][ty * 8];
            float4 a1 = *(float4*)&As[cur][k][ty * 8 + 4];
            float4 b0 = *(float4*)&Bs[cur][k][tx * 8];
            float4 b1 = *(float4*)&Bs[cur][k][tx * 8 + 4];
            float ra[8] = {a0.x, a0.y, a0.z, a0.w, a1.x, a1.y, a1.z, a1.w};
            float rb[8] = {b0.x, b0.y, b0.z, b0.w, b1.x, b1.y, b1.z, b1.w};
            #pragma unroll
            for (int i = 0; i < 8; i++)
                #pragma unroll
                for (int j = 0; j < 8; j++) acc[i][j] = fmaf(ra[i], rb[j], acc[i][j]);
        }
        if (more) {
            const int nx = cur ^ 1;
            As[nx][c0 + 0][r0] = na0.x; As[nx][c0 + 1][r0] = na0.y;
            As[nx][c0 + 2][r0] = na0.z; As[nx][c0 + 3][r0] = na0.w;
            As[nx][c1 + 0][r1] = na1.x; As[nx][c1 + 1][r1] = na1.y;
            As[nx][c1 + 2][r1] = na1.z; As[nx][c1 + 3][r1] = na1.w;
            Bs[nx][c0 + 0][r0] = nb0.x; Bs[nx][c0 + 1][r0] = nb0.y;
            Bs[nx][c0 + 2][r0] = nb0.z; Bs[nx][c0 + 3][r0] = nb0.w;
            Bs[nx][c1 + 0][r1] = nb1.x; Bs[nx][c1 + 1][r1] = nb1.y;
            Bs[nx][c1 + 2][r1] = nb1.z; Bs[nx][c1 + 3][r1] = nb1.w;
            __syncthreads();
            cur = nx;
        }
    }

    const int is_i32 = g_mask_is_i32;
    const int* mi = (const int*)maskp;
    const unsigned char* mu8 = (const unsigned char*)maskp;
    const long long base = (long long)blockIdx.z * SS * SS;

    #pragma unroll
    for (int i = 0; i < 8; i++) {
        int row = bm + ty * 8 + i;
        #pragma unroll
        for (int j = 0; j < 8; j++) {
            int col = bn + tx * 8 + j;
            long long idx = base + (long long)row * SS + col;
            bool m = is_i32 ? (mi[idx] != 0) : (mu8[idx] != 0);
            C[(long long)row * SS + col] = m ? -1e16f : acc[i][j] * INV_T;
        }
    }
}

// ---------------------------------------------------------------------------
// LayerNorm (over last dim of 512) + ReLU. One block of 128 threads per row.
// ---------------------------------------------------------------------------
__global__ void ln_relu_kernel(const float* __restrict__ X,
                               const float* __restrict__ g,
                               const float* __restrict__ beta,
                               float* __restrict__ Y)
{
    __shared__ float sh[32];
    const long long row = blockIdx.x;
    const float* x = X + row * DD;
    const int t = threadIdx.x;

    float4 xv = *(const float4*)(x + t * 4);
    float s  = xv.x + xv.y + xv.z + xv.w;
    float sq = xv.x * xv.x + xv.y * xv.y + xv.z * xv.z + xv.w * xv.w;
    s  = blockReduceSum(s, sh);
    sq = blockReduceSum(sq, sh);
    const float mu  = s * (1.0f / DD);
    const float var = sq * (1.0f / DD) - mu * mu;
    const float r = rsqrtf(var + LN_EPS);

    float4 gv = *(const float4*)(g + t * 4);
    float4 bv = *(const float4*)(beta + t * 4);
    float4 y;
    y.x = fmaxf((xv.x - mu) * r * gv.x + bv.x, 0.0f);
    y.y = fmaxf((xv.y - mu) * r * gv.y + bv.y, 0.0f);
    y.z = fmaxf((xv.z - mu) * r * gv.z + bv.z, 0.0f);
    y.w = fmaxf((xv.w - mu) * r * gv.w + bv.w, 0.0f);
    *(float4*)(Y + row * DD + t * 4) = y;
}

// ---------------------------------------------------------------------------
// Negated softmax over rows of 2048, in place. One block (256 thr) per row.
// ---------------------------------------------------------------------------
__global__ void softmax_neg_kernel(float* __restrict__ P) {
    __shared__ float sh[32];
    float* p = P + (long long)blockIdx.x * SS;
    const int t = threadIdx.x;

    float4 x0 = *(float4*)(p + t * 8);
    float4 x1 = *(float4*)(p + t * 8 + 4);
    float mx = fmaxf(fmaxf(fmaxf(x0.x, x0.y), fmaxf(x0.z, x0.w)),
                     fmaxf(fmaxf(x1.x, x1.y), fmaxf(x1.z, x1.w)));
    mx = blockReduceMax(mx, sh);

    float e[8];
    e[0] = __expf(x0.x - mx); e[1] = __expf(x0.y - mx);
    e[2] = __expf(x0.z - mx); e[3] = __expf(x0.w - mx);
    e[4] = __expf(x1.x - mx); e[5] = __expf(x1.y - mx);
    e[6] = __expf(x1.z - mx); e[7] = __expf(x1.w - mx);
    float s = e[0] + e[1] + e[2] + e[3] + e[4] + e[5] + e[6] + e[7];
    s = blockReduceSum(s, sh);
    const float inv = -1.0f / s;

    x0.x = e[0] * inv; x0.y = e[1] * inv; x0.z = e[2] * inv; x0.w = e[3] * inv;
    x1.x = e[4] * inv; x1.y = e[5] * inv; x1.z = e[6] * inv; x1.w = e[7] * inv;
    *(float4*)(p + t * 8)     = x0;
    *(float4*)(p + t * 8 + 4) = x1;
}

// ---------------------------------------------------------------------------
// Launch
// ---------------------------------------------------------------------------
extern "C" void kernel_launch(void* const* d_in, const int* in_sizes, int n_in,
                              void* d_out, int out_size)
{
    const float* q   = (const float*)d_in[0];
    const float* k   = (const float*)d_in[1];
    const float* v   = (const float*)d_in[2];
    const void*  mask = d_in[3];
    const float* qw1 = (const float*)d_in[4];
    const float* qw2 = (const float*)d_in[5];
    const float* qw3 = (const float*)d_in[6];
    const float* kw1 = (const float*)d_in[7];
    const float* kw2 = (const float*)d_in[8];
    const float* kw3 = (const float*)d_in[9];
    const float* qb1 = (const float*)d_in[10];
    const float* qb2 = (const float*)d_in[11];
    const float* qb3 = (const float*)d_in[12];
    const float* kb1 = (const float*)d_in[13];
    const float* kb2 = (const float*)d_in[14];
    const float* kb3 = (const float*)d_in[15];
    const float* q_ln_b = (const float*)d_in[16];
    const float* k_ln_b = (const float*)d_in[17];
    const float* q_ln_g = (const float*)d_in[18];
    const float* k_ln_g = (const float*)d_in[19];

    float* out  = (float*)d_out;                              // [B,S,D]
    float* attn = out + (long long)BB * SS * DD;              // [B,S,S]

    float *h1, *h2, *dq, *dk;
    cudaGetSymbolAddress((void**)&h1, g_h1);
    cudaGetSymbolAddress((void**)&h2, g_h2);
    cudaGetSymbolAddress((void**)&dq, g_dq);
    cudaGetSymbolAddress((void**)&dk, g_dk);

    detect_mask_kernel<<<1, 256>>>((const unsigned char*)mask);

    const dim3 gMLP(DD / 128, MFULL / 128, 1);   // (4, 128, 1)
    const dim3 blk(256);

    // ---- deep_q ----
    gemm_nn<true,  true><<<gMLP, blk>>>(q,  qw1, qb1, h1, MFULL, DD, DD, 0, 0, 0);
    gemm_nn<false, true><<<gMLP, blk>>>(h1, qw2, qb2, h2, MFULL, DD, DD, 0, 0, 0);
    ln_relu_kernel<<<MFULL, 128>>>(h2, q_ln_g, q_ln_b, h1);
    gemm_nn<false, true><<<gMLP, blk>>>(h1, qw3, qb3, dq, MFULL, DD, DD, 0, 0, 0);

    // ---- deep_k ----
    gemm_nn<true,  true><<<gMLP, blk>>>(k,  kw1, kb1, h1, MFULL, DD, DD, 0, 0, 0);
    gemm_nn<false, true><<<gMLP, blk>>>(h1, kw2, kb2, h2, MFULL, DD, DD, 0, 0, 0);
    ln_relu_kernel<<<MFULL, 128>>>(h2, k_ln_g, k_ln_b, h1);
    gemm_nn<false, true><<<gMLP, blk>>>(h1, kw3, kb3, dk, MFULL, DD, DD, 0, 0, 0);

    // ---- attention ----
    gemm_nt_mask<<<dim3(SS / 128, SS / 128, BB), blk>>>(dq, dk, attn, mask);
    softmax_neg_kernel<<<MFULL, 256>>>(attn);
    gemm_nn<false, false><<<dim3(DD / 128, SS / 128, BB), blk>>>(
        attn, v, nullptr, out, SS, DD, SS,
        (long long)SS * SS, (long long)SS * DD, (long long)SS * DD);
}

// round 3
// speedup vs baseline: 2.4465x; 2.4465x over previous
#include <cuda_runtime.h>
#include <math.h>
#include <stdint.h>

// Problem constants
#define BB 8
#define SS 2048
#define DD 512
#define MFULL (BB * SS)          // 16384
#define INV_T (1.0f / 22.627416997969522f)
#define LN_EPS 1e-5f

// ---------------------------------------------------------------------------
// Scratch (device globals; no allocations allowed)
// ---------------------------------------------------------------------------
__device__ float g_h1[MFULL * DD];
__device__ float g_h2[MFULL * DD];
__device__ float g_dq[MFULL * DD];
__device__ float g_dk[MFULL * DD];
__device__ int   g_mask_is_i32;

// ---------------------------------------------------------------------------
// Mask dtype detector
// ---------------------------------------------------------------------------
__global__ void detect_mask_kernel(const unsigned char* __restrict__ mb) {
    __shared__ int any;
    if (threadIdx.x == 0) any = 0;
    __syncthreads();
    for (int i = threadIdx.x; i < 4096; i += blockDim.x) {
        if ((i & 3) && mb[i]) atomicOr(&any, 1);
    }
    __syncthreads();
    if (threadIdx.x == 0) g_mask_is_i32 = any ? 0 : 1;
}

// ---------------------------------------------------------------------------
// tf32 helpers
// ---------------------------------------------------------------------------
__device__ __forceinline__ float to_tf32(float x) {
    uint32_t r;
    asm("cvt.rna.tf32.f32 %0, %1;" : "=r"(r) : "f"(x));
    return __uint_as_float(r);
}

__device__ __forceinline__ void mma_tf32(float4& d,
    uint32_t a0, uint32_t a1, uint32_t a2, uint32_t a3,
    uint32_t b0, uint32_t b1)
{
    asm volatile(
        "mma.sync.aligned.m16n8k8.row.col.f32.tf32.tf32.f32 "
        "{%0,%1,%2,%3}, {%4,%5,%6,%7}, {%8,%9}, {%0,%1,%2,%3};\n"
        : "+f"(d.x), "+f"(d.y), "+f"(d.z), "+f"(d.w)
        : "r"(a0), "r"(a1), "r"(a2), "r"(a3), "r"(b0), "r"(b1));
}

// ---------------------------------------------------------------------------
// Block reductions
// ---------------------------------------------------------------------------
__device__ __forceinline__ float blockReduceSum(float v, float* sh) {
    #pragma unroll
    for (int o = 16; o > 0; o >>= 1) v += __shfl_xor_sync(0xffffffffu, v, o);
    __syncthreads();
    if ((threadIdx.x & 31) == 0) sh[threadIdx.x >> 5] = v;
    __syncthreads();
    if (threadIdx.x < 32) {
        v = (threadIdx.x < (blockDim.x >> 5)) ? sh[threadIdx.x] : 0.0f;
        #pragma unroll
        for (int o = 16; o > 0; o >>= 1) v += __shfl_xor_sync(0xffffffffu, v, o);
        if (threadIdx.x == 0) sh[0] = v;
    }
    __syncthreads();
    return sh[0];
}

__device__ __forceinline__ float blockReduceMax(float v, float* sh) {
    #pragma unroll
    for (int o = 16; o > 0; o >>= 1) v = fmaxf(v, __shfl_xor_sync(0xffffffffu, v, o));
    __syncthreads();
    if ((threadIdx.x & 31) == 0) sh[threadIdx.x >> 5] = v;
    __syncthreads();
    if (threadIdx.x < 32) {
        v = (threadIdx.x < (blockDim.x >> 5)) ? sh[threadIdx.x] : -3.0e38f;
        #pragma unroll
        for (int o = 16; o > 0; o >>= 1) v = fmaxf(v, __shfl_xor_sync(0xffffffffu, v, o));
        if (threadIdx.x == 0) sh[0] = v;
    }
    __syncthreads();
    return sh[0];
}

// ===========================================================================
// Tensor-core NN GEMM: C[m,n] = sum_k A[m,k]*B[k,n] (+bias)(+relu)
// 128x128 block tile, 256 thr = 8 warps (4m x 2n), warp tile 32x64.
// K-tile 16, double-buffered smem, tf32 mma m16n8k8.
// Batched via blockIdx.z (element strides sA/sB/sC).
// ===========================================================================
template<bool RELU, bool HAS_BIAS>
__global__ void __launch_bounds__(256) gemm_nn_tc(
    const float* __restrict__ Ag, const float* __restrict__ Bg,
    const float* __restrict__ bias, float* __restrict__ Cg,
    int N, int K, long long sA, long long sB, long long sC)
{
    const float* A  = Ag + (long long)blockIdx.z * sA;
    const float* Bm = Bg + (long long)blockIdx.z * sB;
    float* C        = Cg + (long long)blockIdx.z * sC;

    __shared__ float As[2][16][132];   // [k][m], padded
    __shared__ float Bs[2][16][132];   // [k][n], padded

    const int tid  = threadIdx.x;
    const int lane = tid & 31;
    const int warp = tid >> 5;
    const int wm = (warp >> 1) * 32;   // warp m offset in block tile
    const int wn = (warp & 1) * 64;    // warp n offset
    const int bm = blockIdx.y * 128;
    const int bn = blockIdx.x * 128;

    // A loader indices (scatter-transpose): 512 float4 per tile, 2 per thread
    const int a_m0 = tid >> 2,          a_k0 = (tid & 3) * 4;
    const int a_m1 = (tid + 256) >> 2,  a_k1 = ((tid + 256) & 3) * 4;
    // B loader indices (direct): 512 float4 per tile
    const int b_k0 = tid >> 5,          b_n0 = (tid & 31) * 4;
    const int b_k1 = (tid + 256) >> 5,  b_n1 = ((tid + 256) & 31) * 4;

    float4 acc[2][8];
    #pragma unroll
    for (int i = 0; i < 2; i++)
        #pragma unroll
        for (int j = 0; j < 8; j++) acc[i][j] = make_float4(0.f, 0.f, 0.f, 0.f);

    const int numT = K / 16;

    float4 pa0, pa1, pb0, pb1;
    // tile 0 loads
    pa0 = *(const float4*)(A + (long long)(bm + a_m0) * K + a_k0);
    pa1 = *(const float4*)(A + (long long)(bm + a_m1) * K + a_k1);
    pb0 = *(const float4*)(Bm + (long long)b_k0 * N + bn + b_n0);
    pb1 = *(const float4*)(Bm + (long long)b_k1 * N + bn + b_n1);
    // stage into buffer 0
    As[0][a_k0 + 0][a_m0] = to_tf32(pa0.x); As[0][a_k0 + 1][a_m0] = to_tf32(pa0.y);
    As[0][a_k0 + 2][a_m0] = to_tf32(pa0.z); As[0][a_k0 + 3][a_m0] = to_tf32(pa0.w);
    As[0][a_k1 + 0][a_m1] = to_tf32(pa1.x); As[0][a_k1 + 1][a_m1] = to_tf32(pa1.y);
    As[0][a_k1 + 2][a_m1] = to_tf32(pa1.z); As[0][a_k1 + 3][a_m1] = to_tf32(pa1.w);
    {
        float4 t0 = make_float4(to_tf32(pb0.x), to_tf32(pb0.y), to_tf32(pb0.z), to_tf32(pb0.w));
        float4 t1 = make_float4(to_tf32(pb1.x), to_tf32(pb1.y), to_tf32(pb1.z), to_tf32(pb1.w));
        *(float4*)&Bs[0][b_k0][b_n0] = t0;
        *(float4*)&Bs[0][b_k1][b_n1] = t1;
    }
    __syncthreads();

    int cur = 0;
    for (int t = 0; t < numT; t++) {
        const bool more = (t + 1 < numT);
        if (more) {
            const int k0 = (t + 1) * 16;
            pa0 = *(const float4*)(A + (long long)(bm + a_m0) * K + k0 + a_k0);
            pa1 = *(const float4*)(A + (long long)(bm + a_m1) * K + k0 + a_k1);
            pb0 = *(const float4*)(Bm + (long long)(k0 + b_k0) * N + bn + b_n0);
            pb1 = *(const float4*)(Bm + (long long)(k0 + b_k1) * N + bn + b_n1);
        }
        #pragma unroll
        for (int s = 0; s < 2; s++) {
            const int kb = s * 8;
            const int ck = kb + (lane & 3);
            uint32_t af[2][4];
            #pragma unroll
            for (int i = 0; i < 2; i++) {
                const int r = wm + i * 16 + (lane >> 2);
                af[i][0] = __float_as_uint(As[cur][ck][r]);
                af[i][1] = __float_as_uint(As[cur][ck][r + 8]);
                af[i][2] = __float_as_uint(As[cur][ck + 4][r]);
                af[i][3] = __float_as_uint(As[cur][ck + 4][r + 8]);
            }
            #pragma unroll
            for (int j = 0; j < 8; j++) {
                const int n = wn + j * 8 + (lane >> 2);
                const uint32_t bf0 = __float_as_uint(Bs[cur][ck][n]);
                const uint32_t bf1 = __float_as_uint(Bs[cur][ck + 4][n]);
                mma_tf32(acc[0][j], af[0][0], af[0][1], af[0][2], af[0][3], bf0, bf1);
                mma_tf32(acc[1][j], af[1][0], af[1][1], af[1][2], af[1][3], bf0, bf1);
            }
        }
        if (more) {
            const int nx = cur ^ 1;
            As[nx][a_k0 + 0][a_m0] = to_tf32(pa0.x); As[nx][a_k0 + 1][a_m0] = to_tf32(pa0.y);
            As[nx][a_k0 + 2][a_m0] = to_tf32(pa0.z); As[nx][a_k0 + 3][a_m0] = to_tf32(pa0.w);
            As[nx][a_k1 + 0][a_m1] = to_tf32(pa1.x); As[nx][a_k1 + 1][a_m1] = to_tf32(pa1.y);
            As[nx][a_k1 + 2][a_m1] = to_tf32(pa1.z); As[nx][a_k1 + 3][a_m1] = to_tf32(pa1.w);
            float4 t0 = make_float4(to_tf32(pb0.x), to_tf32(pb0.y), to_tf32(pb0.z), to_tf32(pb0.w));
            float4 t1 = make_float4(to_tf32(pb1.x), to_tf32(pb1.y), to_tf32(pb1.z), to_tf32(pb1.w));
            *(float4*)&Bs[nx][b_k0][b_n0] = t0;
            *(float4*)&Bs[nx][b_k1][b_n1] = t1;
            __syncthreads();
            cur = nx;
        }
    }

    // Epilogue: fragment c0:(r,c) c1:(r,c+1) c2:(r+8,c) c3:(r+8,c+1)
    #pragma unroll
    for (int i = 0; i < 2; i++) {
        const int r0 = bm + wm + i * 16 + (lane >> 2);
        const int r1 = r0 + 8;
        #pragma unroll
        for (int j = 0; j < 8; j++) {
            const int c = bn + wn + j * 8 + (lane & 3) * 2;
            float2 v0 = make_float2(acc[i][j].x, acc[i][j].y);
            float2 v1 = make_float2(acc[i][j].z, acc[i][j].w);
            if (HAS_BIAS) {
                const float2 b = *(const float2*)(bias + c);
                v0.x += b.x; v0.y += b.y;
                v1.x += b.x; v1.y += b.y;
            }
            if (RELU) {
                v0.x = fmaxf(v0.x, 0.f); v0.y = fmaxf(v0.y, 0.f);
                v1.x = fmaxf(v1.x, 0.f); v1.y = fmaxf(v1.y, 0.f);
            }
            *(float2*)(C + (long long)r0 * N + c) = v0;
            *(float2*)(C + (long long)r1 * N + c) = v1;
        }
    }
}

// ===========================================================================
// Tensor-core NT GEMM with scale+mask epilogue:
// attn[b,s,t] = mask ? -1e16 : (dq[b,s,:].dk[b,t,:]) * INV_T
// A,B both row-major [rows][K=512]. Same tiling as above; B scatter-loaded.
// ===========================================================================
__global__ void __launch_bounds__(256) gemm_nt_mask_tc(
    const float* __restrict__ Ag, const float* __restrict__ Bg,
    float* __restrict__ Cg, const void* __restrict__ maskp)
{
    const float* A  = Ag + (long long)blockIdx.z * SS * DD;
    const float* Bm = Bg + (long long)blockIdx.z * SS * DD;
    float* C        = Cg + (long long)blockIdx.z * SS * SS;

    __shared__ float As[2][16][132];
    __shared__ float Bs[2][16][132];

    const int tid  = threadIdx.x;
    const int lane = tid & 31;
    const int warp = tid >> 5;
    const int wm = (warp >> 1) * 32;
    const int wn = (warp & 1) * 64;
    const int bm = blockIdx.y * 128;
    const int bn = blockIdx.x * 128;

    const int a_m0 = tid >> 2,          a_k0 = (tid & 3) * 4;
    const int a_m1 = (tid + 256) >> 2,  a_k1 = ((tid + 256) & 3) * 4;

    float4 acc[2][8];
    #pragma unroll
    for (int i = 0; i < 2; i++)
        #pragma unroll
        for (int j = 0; j < 8; j++) acc[i][j] = make_float4(0.f, 0.f, 0.f, 0.f);

    const int numT = DD / 16;

    float4 pa0, pa1, pb0, pb1;
    pa0 = *(const float4*)(A + (long long)(bm + a_m0) * DD + a_k0);
    pa1 = *(const float4*)(A + (long long)(bm + a_m1) * DD + a_k1);
    pb0 = *(const float4*)(Bm + (long long)(bn + a_m0) * DD + a_k0);
    pb1 = *(const float4*)(Bm + (long long)(bn + a_m1) * DD + a_k1);
    As[0][a_k0 + 0][a_m0] = to_tf32(pa0.x); As[0][a_k0 + 1][a_m0] = to_tf32(pa0.y);
    As[0][a_k0 + 2][a_m0] = to_tf32(pa0.z); As[0][a_k0 + 3][a_m0] = to_tf32(pa0.w);
    As[0][a_k1 + 0][a_m1] = to_tf32(pa1.x); As[0][a_k1 + 1][a_m1] = to_tf32(pa1.y);
    As[0][a_k1 + 2][a_m1] = to_tf32(pa1.z); As[0][a_k1 + 3][a_m1] = to_tf32(pa1.w);
    Bs[0][a_k0 + 0][a_m0] = to_tf32(pb0.x); Bs[0][a_k0 + 1][a_m0] = to_tf32(pb0.y);
    Bs[0][a_k0 + 2][a_m0] = to_tf32(pb0.z); Bs[0][a_k0 + 3][a_m0] = to_tf32(pb0.w);
    Bs[0][a_k1 + 0][a_m1] = to_tf32(pb1.x); Bs[0][a_k1 + 1][a_m1] = to_tf32(pb1.y);
    Bs[0][a_k1 + 2][a_m1] = to_tf32(pb1.z); Bs[0][a_k1 + 3][a_m1] = to_tf32(pb1.w);
    __syncthreads();

    int cur = 0;
    for (int t = 0; t < numT; t++) {
        const bool more = (t + 1 < numT);
        if (more) {
            const int k0 = (t + 1) * 16;
            pa0 = *(const float4*)(A + (long long)(bm + a_m0) * DD + k0 + a_k0);
            pa1 = *(const float4*)(A + (long long)(bm + a_m1) * DD + k0 + a_k1);
            pb0 = *(const float4*)(Bm + (long long)(bn + a_m0) * DD + k0 + a_k0);
            pb1 = *(const float4*)(Bm + (long long)(bn + a_m1) * DD + k0 + a_k1);
        }
        #pragma unroll
        for (int s = 0; s < 2; s++) {
            const int kb = s * 8;
            const int ck = kb + (lane & 3);
            uint32_t af[2][4];
            #pragma unroll
            for (int i = 0; i < 2; i++) {
                const int r = wm + i * 16 + (lane >> 2);
                af[i][0] = __float_as_uint(As[cur][ck][r]);
                af[i][1] = __float_as_uint(As[cur][ck][r + 8]);
                af[i][2] = __float_as_uint(As[cur][ck + 4][r]);
                af[i][3] = __float_as_uint(As[cur][ck + 4][r + 8]);
            }
            #pragma unroll
            for (int j = 0; j < 8; j++) {
                const int n = wn + j * 8 + (lane >> 2);
                const uint32_t bf0 = __float_as_uint(Bs[cur][ck][n]);
                const uint32_t bf1 = __float_as_uint(Bs[cur][ck + 4][n]);
                mma_tf32(acc[0][j], af[0][0], af[0][1], af[0][2], af[0][3], bf0, bf1);
                mma_tf32(acc[1][j], af[1][0], af[1][1], af[1][2], af[1][3], bf0, bf1);
            }
        }
        if (more) {
            const int nx = cur ^ 1;
            As[nx][a_k0 + 0][a_m0] = to_tf32(pa0.x); As[nx][a_k0 + 1][a_m0] = to_tf32(pa0.y);
            As[nx][a_k0 + 2][a_m0] = to_tf32(pa0.z); As[nx][a_k0 + 3][a_m0] = to_tf32(pa0.w);
            As[nx][a_k1 + 0][a_m1] = to_tf32(pa1.x); As[nx][a_k1 + 1][a_m1] = to_tf32(pa1.y);
            As[nx][a_k1 + 2][a_m1] = to_tf32(pa1.z); As[nx][a_k1 + 3][a_m1] = to_tf32(pa1.w);
            Bs[nx][a_k0 + 0][a_m0] = to_tf32(pb0.x); Bs[nx][a_k0 + 1][a_m0] = to_tf32(pb0.y);
            Bs[nx][a_k0 + 2][a_m0] = to_tf32(pb0.z); Bs[nx][a_k0 + 3][a_m0] = to_tf32(pb0.w);
            Bs[nx][a_k1 + 0][a_m1] = to_tf32(pb1.x); Bs[nx][a_k1 + 1][a_m1] = to_tf32(pb1.y);
            Bs[nx][a_k1 + 2][a_m1] = to_tf32(pb1.z); Bs[nx][a_k1 + 3][a_m1] = to_tf32(pb1.w);
            __syncthreads();
            cur = nx;
        }
    }

    const int is_i32 = g_mask_is_i32;
    const int* mi = (const int*)maskp;
    const unsigned char* mu8 = (const unsigned char*)maskp;
    const long long base = (long long)blockIdx.z * SS * SS;

    #pragma unroll
    for (int i = 0; i < 2; i++) {
        const int r0 = bm + wm + i * 16 + (lane >> 2);
        const int r1 = r0 + 8;
        #pragma unroll
        for (int j = 0; j < 8; j++) {
            const int c = bn + wn + j * 8 + (lane & 3) * 2;
            const long long i00 = base + (long long)r0 * SS + c;
            const long long i10 = base + (long long)r1 * SS + c;
            bool m00, m01, m10, m11;
            if (is_i32) {
                m00 = mi[i00] != 0; m01 = mi[i00 + 1] != 0;
                m10 = mi[i10] != 0; m11 = mi[i10 + 1] != 0;
            } else {
                m00 = mu8[i00] != 0; m01 = mu8[i00 + 1] != 0;
                m10 = mu8[i10] != 0; m11 = mu8[i10 + 1] != 0;
            }
            float2 v0, v1;
            v0.x = m00 ? -1e16f : acc[i][j].x * INV_T;
            v0.y = m01 ? -1e16f : acc[i][j].y * INV_T;
            v1.x = m10 ? -1e16f : acc[i][j].z * INV_T;
            v1.y = m11 ? -1e16f : acc[i][j].w * INV_T;
            *(float2*)(C + (long long)r0 * SS + c) = v0;
            *(float2*)(C + (long long)r1 * SS + c) = v1;
        }
    }
}

// ---------------------------------------------------------------------------
// LayerNorm + ReLU
// ---------------------------------------------------------------------------
__global__ void ln_relu_kernel(const float* __restrict__ X,
                               const float* __restrict__ g,
                               const float* __restrict__ beta,
                               float* __restrict__ Y)
{
    __shared__ float sh[32];
    const long long row = blockIdx.x;
    const float* x = X + row * DD;
    const int t = threadIdx.x;

    float4 xv = *(const float4*)(x + t * 4);
    float s  = xv.x + xv.y + xv.z + xv.w;
    float sq = xv.x * xv.x + xv.y * xv.y + xv.z * xv.z + xv.w * xv.w;
    s  = blockReduceSum(s, sh);
    sq = blockReduceSum(sq, sh);
    const float mu  = s * (1.0f / DD);
    const float var = sq * (1.0f / DD) - mu * mu;
    const float r = rsqrtf(var + LN_EPS);

    float4 gv = *(const float4*)(g + t * 4);
    float4 bv = *(const float4*)(beta + t * 4);
    float4 y;
    y.x = fmaxf((xv.x - mu) * r * gv.x + bv.x, 0.0f);
    y.y = fmaxf((xv.y - mu) * r * gv.y + bv.y, 0.0f);
    y.z = fmaxf((xv.z - mu) * r * gv.z + bv.z, 0.0f);
    y.w = fmaxf((xv.w - mu) * r * gv.w + bv.w, 0.0f);
    *(float4*)(Y + row * DD + t * 4) = y;
}

// ---------------------------------------------------------------------------
// Negated softmax over rows of 2048, in place.
// ---------------------------------------------------------------------------
__global__ void softmax_neg_kernel(float* __restrict__ P) {
    __shared__ float sh[32];
    float* p = P + (long long)blockIdx.x * SS;
    const int t = threadIdx.x;

    float4 x0 = *(float4*)(p + t * 8);
    float4 x1 = *(float4*)(p + t * 8 + 4);
    float mx = fmaxf(fmaxf(fmaxf(x0.x, x0.y), fmaxf(x0.z, x0.w)),
                     fmaxf(fmaxf(x1.x, x1.y), fmaxf(x1.z, x1.w)));
    mx = blockReduceMax(mx, sh);

    float e[8];
    e[0] = __expf(x0.x - mx); e[1] = __expf(x0.y - mx);
    e[2] = __expf(x0.z - mx); e[3] = __expf(x0.w - mx);
    e[4] = __expf(x1.x - mx); e[5] = __expf(x1.y - mx);
    e[6] = __expf(x1.z - mx); e[7] = __expf(x1.w - mx);
    float s = e[0] + e[1] + e[2] + e[3] + e[4] + e[5] + e[6] + e[7];
    s = blockReduceSum(s, sh);
    const float inv = -1.0f / s;

    x0.x = e[0] * inv; x0.y = e[1] * inv; x0.z = e[2] * inv; x0.w = e[3] * inv;
    x1.x = e[4] * inv; x1.y = e[5] * inv; x1.z = e[6] * inv; x1.w = e[7] * inv;
    *(float4*)(p + t * 8)     = x0;
    *(float4*)(p + t * 8 + 4) = x1;
}

// ---------------------------------------------------------------------------
// Launch
// ---------------------------------------------------------------------------
extern "C" void kernel_launch(void* const* d_in, const int* in_sizes, int n_in,
                              void* d_out, int out_size)
{
    const float* q   = (const float*)d_in[0];
    const float* k   = (const float*)d_in[1];
    const float* v   = (const float*)d_in[2];
    const void*  mask = d_in[3];
    const float* qw1 = (const float*)d_in[4];
    const float* qw2 = (const float*)d_in[5];
    const float* qw3 = (const float*)d_in[6];
    const float* kw1 = (const float*)d_in[7];
    const float* kw2 = (const float*)d_in[8];
    const float* kw3 = (const float*)d_in[9];
    const float* qb1 = (const float*)d_in[10];
    const float* qb2 = (const float*)d_in[11];
    const float* qb3 = (const float*)d_in[12];
    const float* kb1 = (const float*)d_in[13];
    const float* kb2 = (const float*)d_in[14];
    const float* kb3 = (const float*)d_in[15];
    const float* q_ln_b = (const float*)d_in[16];
    const float* k_ln_b = (const float*)d_in[17];
    const float* q_ln_g = (const float*)d_in[18];
    const float* k_ln_g = (const float*)d_in[19];

    float* out  = (float*)d_out;                              // [B,S,D]
    float* attn = out + (long long)BB * SS * DD;              // [B,S,S]

    float *h1, *h2, *dq, *dk;
    cudaGetSymbolAddress((void**)&h1, g_h1);
    cudaGetSymbolAddress((void**)&h2, g_h2);
    cudaGetSymbolAddress((void**)&dq, g_dq);
    cudaGetSymbolAddress((void**)&dk, g_dk);

    detect_mask_kernel<<<1, 256>>>((const unsigned char*)mask);

    const dim3 gMLP(DD / 128, MFULL / 128, 1);   // (4, 128, 1)
    const dim3 blk(256);

    // ---- deep_q ----
    gemm_nn_tc<true,  true><<<gMLP, blk>>>(q,  qw1, qb1, h1, DD, DD, 0, 0, 0);
    gemm_nn_tc<false, true><<<gMLP, blk>>>(h1, qw2, qb2, h2, DD, DD, 0, 0, 0);
    ln_relu_kernel<<<MFULL, 128>>>(h2, q_ln_g, q_ln_b, h1);
    gemm_nn_tc<false, true><<<gMLP, blk>>>(h1, qw3, qb3, dq, DD, DD, 0, 0, 0);

    // ---- deep_k ----
    gemm_nn_tc<true,  true><<<gMLP, blk>>>(k,  kw1, kb1, h1, DD, DD, 0, 0, 0);
    gemm_nn_tc<false, true><<<gMLP, blk>>>(h1, kw2, kb2, h2, DD, DD, 0, 0, 0);
    ln_relu_kernel<<<MFULL, 128>>>(h2, k_ln_g, k_ln_b, h1);
    gemm_nn_tc<false, true><<<gMLP, blk>>>(h1, kw3, kb3, dk, DD, DD, 0, 0, 0);

    // ---- attention ----
    gemm_nt_mask_tc<<<dim3(SS / 128, SS / 128, BB), blk>>>(dq, dk, attn, mask);
    softmax_neg_kernel<<<MFULL, 256>>>(attn);
    gemm_nn_tc<false, false><<<dim3(DD / 128, SS / 128, BB), blk>>>(
        attn, v, nullptr, out, DD, SS,
        (long long)SS * SS, (long long)SS * DD, (long long)SS * DD);
}

// round 5
// speedup vs baseline: 3.5098x; 1.4347x over previous
#include <cuda_runtime.h>
#include <math.h>
#include <stdint.h>

// Problem constants
#define BB 8
#define SS 2048
#define DD 512
#define MFULL (BB * SS)          // 16384
#define INV_T (1.0f / 22.627416997969522f)
#define LN_EPS 1e-5f

// GEMM tiling: 128x128 block tile, K-slab 32, 3-stage cp.async pipeline
#define TKS 32
#define NSTAGE 3
#define ROWSTRIDE 36                          // floats; pad for bank-conflict-free frags
#define A_TILE_FLOATS (128 * ROWSTRIDE)       // 4608
#define STAGE_FLOATS (2 * A_TILE_FLOATS)      // 9216
#define GEMM_SMEM_BYTES (NSTAGE * STAGE_FLOATS * 4)   // 110592

// ---------------------------------------------------------------------------
// Scratch (device globals; no allocations allowed)
// ---------------------------------------------------------------------------
__device__ float g_h1[MFULL * DD];
__device__ float g_h2[MFULL * DD];
__device__ float g_dq[MFULL * DD];
__device__ float g_dk[MFULL * DD];
__device__ float g_wt[6 * DD * DD];     // transposed weights
__device__ float g_vt[BB * DD * SS];    // transposed V per batch: [b][d][t]
__device__ int   g_mask_is_i32;

// ---------------------------------------------------------------------------
// helpers
// ---------------------------------------------------------------------------
__device__ __forceinline__ uint32_t smem_u32(const void* p) {
    uint32_t a;
    asm("{ .reg .u64 t; cvta.to.shared.u64 t, %1; cvt.u32.u64 %0, t; }" : "=r"(a) : "l"(p));
    return a;
}

__device__ __forceinline__ float rnd_tf32(float x) {
    uint32_t r;
    asm("cvt.rna.tf32.f32 %0, %1;" : "=r"(r) : "f"(x));
    return __uint_as_float(r);
}

__device__ __forceinline__ void mma_tf32(float4& d,
    uint32_t a0, uint32_t a1, uint32_t a2, uint32_t a3,
    uint32_t b0, uint32_t b1)
{
    asm volatile(
        "mma.sync.aligned.m16n8k8.row.col.f32.tf32.tf32.f32 "
        "{%0,%1,%2,%3}, {%4,%5,%6,%7}, {%8,%9}, {%0,%1,%2,%3};\n"
        : "+f"(d.x), "+f"(d.y), "+f"(d.z), "+f"(d.w)
        : "r"(a0), "r"(a1), "r"(a2), "r"(a3), "r"(b0), "r"(b1));
}

#define CP_ASYNC16(dst_u32, src_ptr) \
    asm volatile("cp.async.cg.shared.global [%0], [%1], 16;" \
        :: "r"(dst_u32), "l"(src_ptr) : "memory")
#define CP_COMMIT() asm volatile("cp.async.commit_group;" ::: "memory")
#define CP_WAIT(n)  asm volatile("cp.async.wait_group %0;" :: "n"(n) : "memory")

// ---------------------------------------------------------------------------
// Mask dtype detector
// ---------------------------------------------------------------------------
__global__ void detect_mask_kernel(const unsigned char* __restrict__ mb) {
    __shared__ int any;
    if (threadIdx.x == 0) any = 0;
    __syncthreads();
    for (int i = threadIdx.x; i < 4096; i += blockDim.x) {
        if ((i & 3) && mb[i]) atomicOr(&any, 1);
    }
    __syncthreads();
    if (threadIdx.x == 0) g_mask_is_i32 = any ? 0 : 1;
}

// ---------------------------------------------------------------------------
// Tiled transpose: src [R][C] -> dst [C][R]; batched via blockIdx.z
// Optionally rounds to tf32 (rna) on store.
// ---------------------------------------------------------------------------
__global__ void transpose_kernel(const float* __restrict__ S, float* __restrict__ D,
                                 int R, int C, long long sS, long long sD, int rnd) {
    __shared__ float tile[32][33];
    const float* s = S + (long long)blockIdx.z * sS;
    float* d = D + (long long)blockIdx.z * sD;
    const int x = blockIdx.x * 32 + threadIdx.x;
    const int y0 = blockIdx.y * 32;
    #pragma unroll
    for (int i = threadIdx.y; i < 32; i += 8)
        tile[i][threadIdx.x] = s[(long long)(y0 + i) * C + x];
    __syncthreads();
    const int xo = blockIdx.y * 32 + threadIdx.x;
    const int yo0 = blockIdx.x * 32;
    #pragma unroll
    for (int i = threadIdx.y; i < 32; i += 8) {
        float v = tile[threadIdx.x][i];
        if (rnd) v = rnd_tf32(v);
        d[(long long)(yo0 + i) * R + xo] = v;
    }
}

// ===========================================================================
// Multistage tf32 mma.sync NT GEMM:
//   C[m,n] = epilogue( sum_k A[m,k] * B[n,k] )
// A: [M][K] row-major, B: [N][K] row-major. Block tile 128x128, 256 thr,
// 8 warps (4m x 2n), warp tile 32x64. K-slab 32, 3-stage cp.async.
// EPI: 0 = +bias+relu, 1 = +bias, 2 = QK mask/scale, 3 = plain
// RND: round outputs to tf32 (rna) before store.
// ===========================================================================
template<int EPI, bool RND>
__global__ void __launch_bounds__(256, 2) gemm_ms(
    const float* __restrict__ Ag, const float* __restrict__ Bg,
    const float* __restrict__ bias, float* __restrict__ Cg,
    int K, int ldc, long long sA, long long sB, long long sC,
    const void* __restrict__ maskp)
{
    extern __shared__ float sm[];
    const uint32_t sbase = smem_u32(sm);
    const int tid  = threadIdx.x;
    const int warp = tid >> 5;
    const int lane = tid & 31;
    const int wm = (warp >> 1) * 32;
    const int wn = (warp & 1) * 64;

    const float* A = Ag + (long long)blockIdx.z * sA;
    const float* B = Bg + (long long)blockIdx.z * sB;
    float* C       = Cg + (long long)blockIdx.z * sC;
    const int bm = blockIdx.y * 128;
    const int bn = blockIdx.x * 128;

    // cp.async loader: stage t -> buffer buf. Both tiles are 128 rows x 32 k.
    const int l_m  = tid >> 1;                 // 0..127  (2 chunks of 16B per row... )
    // 128 rows x 8 chunks = 1024 chunks per tile; 4 per thread.
    auto load_stage = [&](int t, int buf) {
        const float* Abase = A + (long long)bm * K + t * TKS;
        const float* Bbase = B + (long long)bn * K + t * TKS;
        const uint32_t s0 = sbase + (uint32_t)(buf * STAGE_FLOATS) * 4u;
        #pragma unroll
        for (int i = 0; i < 4; i++) {
            const int c = tid + i * 256;
            const int m = c >> 3, kc = c & 7;
            CP_ASYNC16(s0 + (uint32_t)(m * ROWSTRIDE + kc * 4) * 4u,
                       Abase + (long long)m * K + kc * 4);
            CP_ASYNC16(s0 + (uint32_t)(A_TILE_FLOATS + m * ROWSTRIDE + kc * 4) * 4u,
                       Bbase + (long long)m * K + kc * 4);
        }
    };
    (void)l_m;

    float4 acc[2][8];
    #pragma unroll
    for (int i = 0; i < 2; i++)
        #pragma unroll
        for (int j = 0; j < 8; j++) acc[i][j] = make_float4(0.f, 0.f, 0.f, 0.f);

    const int T = K / TKS;

    load_stage(0, 0); CP_COMMIT();
    load_stage(1, 1); CP_COMMIT();

    for (int t = 0; t < T; t++) {
        const int buf = t % NSTAGE;
        CP_WAIT(1);                 // stage t resident
        __syncthreads();
        if (t + 2 < T) load_stage(t + 2, (t + 2) % NSTAGE);
        CP_COMMIT();                // always commit to keep group accounting uniform

        const float* As = sm + buf * STAGE_FLOATS;
        const float* Bs = As + A_TILE_FLOATS;

        #pragma unroll
        for (int ks = 0; ks < 4; ks++) {
            const int ck = ks * 8 + (lane & 3);
            uint32_t af[2][4];
            #pragma unroll
            for (int i = 0; i < 2; i++) {
                const int r = wm + i * 16 + (lane >> 2);
                af[i][0] = __float_as_uint(As[r * ROWSTRIDE + ck]);
                af[i][1] = __float_as_uint(As[(r + 8) * ROWSTRIDE + ck]);
                af[i][2] = __float_as_uint(As[r * ROWSTRIDE + ck + 4]);
                af[i][3] = __float_as_uint(As[(r + 8) * ROWSTRIDE + ck + 4]);
            }
            #pragma unroll
            for (int j = 0; j < 8; j++) {
                const int n = wn + j * 8 + (lane >> 2);
                const uint32_t bf0 = __float_as_uint(Bs[n * ROWSTRIDE + ck]);
                const uint32_t bf1 = __float_as_uint(Bs[n * ROWSTRIDE + ck + 4]);
                mma_tf32(acc[0][j], af[0][0], af[0][1], af[0][2], af[0][3], bf0, bf1);
                mma_tf32(acc[1][j], af[1][0], af[1][1], af[1][2], af[1][3], bf0, bf1);
            }
        }
        __syncthreads();
    }

    // Epilogue: frag c0,c1 -> (r, c..c+1); c2,c3 -> (r+8, c..c+1)
    const int is_i32 = (EPI == 2) ? g_mask_is_i32 : 0;
    #pragma unroll
    for (int i = 0; i < 2; i++) {
        const int r0 = bm + wm + i * 16 + (lane >> 2);
        const int r1 = r0 + 8;
        #pragma unroll
        for (int j = 0; j < 8; j++) {
            const int c = bn + wn + j * 8 + (lane & 3) * 2;
            float2 v0 = make_float2(acc[i][j].x, acc[i][j].y);
            float2 v1 = make_float2(acc[i][j].z, acc[i][j].w);
            if (EPI == 0 || EPI == 1) {
                const float2 b = *(const float2*)(bias + c);
                v0.x += b.x; v0.y += b.y;
                v1.x += b.x; v1.y += b.y;
                if (EPI == 0) {
                    v0.x = fmaxf(v0.x, 0.f); v0.y = fmaxf(v0.y, 0.f);
                    v1.x = fmaxf(v1.x, 0.f); v1.y = fmaxf(v1.y, 0.f);
                }
            } else if (EPI == 2) {
                const long long base = (long long)blockIdx.z * SS * SS;
                const long long i00 = base + (long long)r0 * SS + c;
                const long long i10 = base + (long long)r1 * SS + c;
                bool m00, m01, m10, m11;
                if (is_i32) {
                    const int* mi = (const int*)maskp;
                    m00 = mi[i00] != 0; m01 = mi[i00 + 1] != 0;
                    m10 = mi[i10] != 0; m11 = mi[i10 + 1] != 0;
                } else {
                    const unsigned char* mu = (const unsigned char*)maskp;
                    m00 = mu[i00] != 0; m01 = mu[i00 + 1] != 0;
                    m10 = mu[i10] != 0; m11 = mu[i10 + 1] != 0;
                }
                v0.x = m00 ? -1e16f : v0.x * INV_T;
                v0.y = m01 ? -1e16f : v0.y * INV_T;
                v1.x = m10 ? -1e16f : v1.x * INV_T;
                v1.y = m11 ? -1e16f : v1.y * INV_T;
            }
            if (RND) {
                v0.x = rnd_tf32(v0.x); v0.y = rnd_tf32(v0.y);
                v1.x = rnd_tf32(v1.x); v1.y = rnd_tf32(v1.y);
            }
            *(float2*)(C + (long long)r0 * ldc + c) = v0;
            *(float2*)(C + (long long)r1 * ldc + c) = v1;
        }
    }
}

// ---------------------------------------------------------------------------
// Block reductions
// ---------------------------------------------------------------------------
__device__ __forceinline__ float blockReduceSum(float v, float* sh) {
    #pragma unroll
    for (int o = 16; o > 0; o >>= 1) v += __shfl_xor_sync(0xffffffffu, v, o);
    __syncthreads();
    if ((threadIdx.x & 31) == 0) sh[threadIdx.x >> 5] = v;
    __syncthreads();
    if (threadIdx.x < 32) {
        v = (threadIdx.x < (blockDim.x >> 5)) ? sh[threadIdx.x] : 0.0f;
        #pragma unroll
        for (int o = 16; o > 0; o >>= 1) v += __shfl_xor_sync(0xffffffffu, v, o);
        if (threadIdx.x == 0) sh[0] = v;
    }
    __syncthreads();
    return sh[0];
}

__device__ __forceinline__ float blockReduceMax(float v, float* sh) {
    #pragma unroll
    for (int o = 16; o > 0; o >>= 1) v = fmaxf(v, __shfl_xor_sync(0xffffffffu, v, o));
    __syncthreads();
    if ((threadIdx.x & 31) == 0) sh[threadIdx.x >> 5] = v;
    __syncthreads();
    if (threadIdx.x < 32) {
        v = (threadIdx.x < (blockDim.x >> 5)) ? sh[threadIdx.x] : -3.0e38f;
        #pragma unroll
        for (int o = 16; o > 0; o >>= 1) v = fmaxf(v, __shfl_xor_sync(0xffffffffu, v, o));
        if (threadIdx.x == 0) sh[0] = v;
    }
    __syncthreads();
    return sh[0];
}

// ---------------------------------------------------------------------------
// LayerNorm + ReLU (+ tf32 rounding of output — feeds layer-3 GEMM)
// ---------------------------------------------------------------------------
__global__ void ln_relu_kernel(const float* __restrict__ X,
                               const float* __restrict__ g,
                               const float* __restrict__ beta,
                               float* __restrict__ Y)
{
    __shared__ float sh[32];
    const long long row = blockIdx.x;
    const float* x = X + row * DD;
    const int t = threadIdx.x;

    float4 xv = *(const float4*)(x + t * 4);
    float s  = xv.x + xv.y + xv.z + xv.w;
    float sq = xv.x * xv.x + xv.y * xv.y + xv.z * xv.z + xv.w * xv.w;
    s  = blockReduceSum(s, sh);
    sq = blockReduceSum(sq, sh);
    const float mu  = s * (1.0f / DD);
    const float var = sq * (1.0f / DD) - mu * mu;
    const float r = rsqrtf(var + LN_EPS);

    float4 gv = *(const float4*)(g + t * 4);
    float4 bv = *(const float4*)(beta + t * 4);
    float4 y;
    y.x = rnd_tf32(fmaxf((xv.x - mu) * r * gv.x + bv.x, 0.0f));
    y.y = rnd_tf32(fmaxf((xv.y - mu) * r * gv.y + bv.y, 0.0f));
    y.z = rnd_tf32(fmaxf((xv.z - mu) * r * gv.z + bv.z, 0.0f));
    y.w = rnd_tf32(fmaxf((xv.w - mu) * r * gv.w + bv.w, 0.0f));
    *(float4*)(Y + row * DD + t * 4) = y;
}

// ---------------------------------------------------------------------------
// Negated softmax over rows of 2048, in place (final attn output — exact fp32)
// ---------------------------------------------------------------------------
__global__ void softmax_neg_kernel(float* __restrict__ P) {
    __shared__ float sh[32];
    float* p = P + (long long)blockIdx.x * SS;
    const int t = threadIdx.x;

    float4 x0 = *(float4*)(p + t * 8);
    float4 x1 = *(float4*)(p + t * 8 + 4);
    float mx = fmaxf(fmaxf(fmaxf(x0.x, x0.y), fmaxf(x0.z, x0.w)),
                     fmaxf(fmaxf(x1.x, x1.y), fmaxf(x1.z, x1.w)));
    mx = blockReduceMax(mx, sh);

    float e[8];
    e[0] = __expf(x0.x - mx); e[1] = __expf(x0.y - mx);
    e[2] = __expf(x0.z - mx); e[3] = __expf(x0.w - mx);
    e[4] = __expf(x1.x - mx); e[5] = __expf(x1.y - mx);
    e[6] = __expf(x1.z - mx); e[7] = __expf(x1.w - mx);
    float s = e[0] + e[1] + e[2] + e[3] + e[4] + e[5] + e[6] + e[7];
    s = blockReduceSum(s, sh);
    const float inv = -1.0f / s;

    x0.x = e[0] * inv; x0.y = e[1] * inv; x0.z = e[2] * inv; x0.w = e[3] * inv;
    x1.x = e[4] * inv; x1.y = e[5] * inv; x1.z = e[6] * inv; x1.w = e[7] * inv;
    *(float4*)(p + t * 8)     = x0;
    *(float4*)(p + t * 8 + 4) = x1;
}

// ---------------------------------------------------------------------------
// Launch
// ---------------------------------------------------------------------------
extern "C" void kernel_launch(void* const* d_in, const int* in_sizes, int n_in,
                              void* d_out, int out_size)
{
    const float* q   = (const float*)d_in[0];
    const float* k   = (const float*)d_in[1];
    const float* v   = (const float*)d_in[2];
    const void*  mask = d_in[3];
    const float* qw1 = (const float*)d_in[4];
    const float* qw2 = (const float*)d_in[5];
    const float* qw3 = (const float*)d_in[6];
    const float* kw1 = (const float*)d_in[7];
    const float* kw2 = (const float*)d_in[8];
    const float* kw3 = (const float*)d_in[9];
    const float* qb1 = (const float*)d_in[10];
    const float* qb2 = (const float*)d_in[11];
    const float* qb3 = (const float*)d_in[12];
    const float* kb1 = (const float*)d_in[13];
    const float* kb2 = (const float*)d_in[14];
    const float* kb3 = (const float*)d_in[15];
    const float* q_ln_b = (const float*)d_in[16];
    const float* k_ln_b = (const float*)d_in[17];
    const float* q_ln_g = (const float*)d_in[18];
    const float* k_ln_g = (const float*)d_in[19];

    float* out  = (float*)d_out;                              // [B,S,D]
    float* attn = out + (long long)BB * SS * DD;              // [B,S,S]

    float *h1, *h2, *dq, *dk, *wt, *vt;
    cudaGetSymbolAddress((void**)&h1, g_h1);
    cudaGetSymbolAddress((void**)&h2, g_h2);
    cudaGetSymbolAddress((void**)&dq, g_dq);
    cudaGetSymbolAddress((void**)&dk, g_dk);
    cudaGetSymbolAddress((void**)&wt, g_wt);
    cudaGetSymbolAddress((void**)&vt, g_vt);

    const size_t shm = GEMM_SMEM_BYTES;
    cudaFuncSetAttribute(gemm_ms<0, false>, cudaFuncAttributeMaxDynamicSharedMemorySize, shm);
    cudaFuncSetAttribute(gemm_ms<1, false>, cudaFuncAttributeMaxDynamicSharedMemorySize, shm);
    cudaFuncSetAttribute(gemm_ms<1, true >, cudaFuncAttributeMaxDynamicSharedMemorySize, shm);
    cudaFuncSetAttribute(gemm_ms<2, false>, cudaFuncAttributeMaxDynamicSharedMemorySize, shm);
    cudaFuncSetAttribute(gemm_ms<3, false>, cudaFuncAttributeMaxDynamicSharedMemorySize, shm);

    detect_mask_kernel<<<1, 256>>>((const unsigned char*)mask);

    // Pre-transpose weights W[k][n] -> Wt[n][k] (tf32-rounded)
    const float* ws[6] = {qw1, qw2, qw3, kw1, kw2, kw3};
    for (int i = 0; i < 6; i++)
        transpose_kernel<<<dim3(16, 16, 1), dim3(32, 8)>>>(
            ws[i], wt + (long long)i * DD * DD, DD, DD, 0, 0, 1);
    float* wtq1 = wt + 0LL * DD * DD; float* wtq2 = wt + 1LL * DD * DD;
    float* wtq3 = wt + 2LL * DD * DD; float* wtk1 = wt + 3LL * DD * DD;
    float* wtk2 = wt + 4LL * DD * DD; float* wtk3 = wt + 5LL * DD * DD;

    // Pre-transpose V per batch: V[b][t][d] -> Vt[b][d][t] (tf32-rounded)
    transpose_kernel<<<dim3(DD / 32, SS / 32, BB), dim3(32, 8)>>>(
        v, vt, SS, DD, (long long)SS * DD, (long long)DD * SS, 1);

    const dim3 gMLP(DD / 128, MFULL / 128, 1);    // (4, 128, 1)

    // ---- deep_q ----
    gemm_ms<0, false><<<gMLP, 256, shm>>>(q,  wtq1, qb1, h1, DD, DD, 0, 0, 0, nullptr);
    gemm_ms<1, false><<<gMLP, 256, shm>>>(h1, wtq2, qb2, h2, DD, DD, 0, 0, 0, nullptr);
    ln_relu_kernel<<<MFULL, 128>>>(h2, q_ln_g, q_ln_b, h1);
    gemm_ms<1, true ><<<gMLP, 256, shm>>>(h1, wtq3, qb3, dq, DD, DD, 0, 0, 0, nullptr);

    // ---- deep_k ----
    gemm_ms<0, false><<<gMLP, 256, shm>>>(k,  wtk1, kb1, h1, DD, DD, 0, 0, 0, nullptr);
    gemm_ms<1, false><<<gMLP, 256, shm>>>(h1, wtk2, kb2, h2, DD, DD, 0, 0, 0, nullptr);
    ln_relu_kernel<<<MFULL, 128>>>(h2, k_ln_g, k_ln_b, h1);
    gemm_ms<1, true ><<<gMLP, 256, shm>>>(h1, wtk3, kb3, dk, DD, DD, 0, 0, 0, nullptr);

    // ---- attention ----
    gemm_ms<2, false><<<dim3(SS / 128, SS / 128, BB), 256, shm>>>(
        dq, dk, nullptr, attn, DD, SS,
        (long long)SS * DD, (long long)SS * DD, (long long)SS * SS, mask);
    softmax_neg_kernel<<<MFULL, 256>>>(attn);
    gemm_ms<3, false><<<dim3(DD / 128, SS / 128, BB), 256, shm>>>(
        attn, vt, nullptr, out, SS, DD,
        (long long)SS * SS, (long long)DD * SS, (long long)SS * DD, nullptr);
}

// round 7
// speedup vs baseline: 5.4235x; 1.5452x over previous
#include <cuda_runtime.h>
#include <cuda_fp16.h>
#include <math.h>
#include <stdint.h>

// Problem constants
#define BB 8
#define SS 2048
#define DD 512
#define MFULL (BB * SS)          // 16384
#define INV_T (1.0f / 22.627416997969522f)
#define LN_EPS 1e-5f

// GEMM tiling: 128x128 block tile, K-slab 64 (halves), 3-stage cp.async
#define TKS 64
#define NSTAGE 3
#define RS 72                                  // row stride in halves (64 + 8 pad)
#define TILE_HALVES (128 * RS)                 // 9216
#define STAGE_HALVES (2 * TILE_HALVES)         // 18432
#define GEMM_SMEM_BYTES (NSTAGE * STAGE_HALVES * 2)   // 110592

// ---------------------------------------------------------------------------
// Scratch (device globals; no allocations allowed)
// ---------------------------------------------------------------------------
__device__ __half g_qh[MFULL * DD];
__device__ __half g_kh[MFULL * DD];
__device__ __half g_t1[MFULL * DD];
__device__ __half g_t2[MFULL * DD];
__device__ __half g_dq[MFULL * DD];
__device__ __half g_dk[MFULL * DD];
__device__ __half g_wt[6 * DD * DD];
__device__ __half g_vt[BB * DD * SS];
__device__ __half g_ah[(long long)BB * SS * SS];
__device__ int    g_mask_is_i32;

// ---------------------------------------------------------------------------
// helpers
// ---------------------------------------------------------------------------
__device__ __forceinline__ uint32_t smem_u32(const void* p) {
    uint32_t a;
    asm("{ .reg .u64 t; cvta.to.shared.u64 t, %1; cvt.u32.u64 %0, t; }" : "=r"(a) : "l"(p));
    return a;
}

__device__ __forceinline__ void mma_f16(float4& d,
    uint32_t a0, uint32_t a1, uint32_t a2, uint32_t a3,
    uint32_t b0, uint32_t b1)
{
    asm volatile(
        "mma.sync.aligned.m16n8k16.row.col.f32.f16.f16.f32 "
        "{%0,%1,%2,%3}, {%4,%5,%6,%7}, {%8,%9}, {%0,%1,%2,%3};\n"
        : "+f"(d.x), "+f"(d.y), "+f"(d.z), "+f"(d.w)
        : "r"(a0), "r"(a1), "r"(a2), "r"(a3), "r"(b0), "r"(b1));
}

#define CP_ASYNC16(dst_u32, src_ptr) \
    asm volatile("cp.async.cg.shared.global [%0], [%1], 16;" \
        :: "r"(dst_u32), "l"(src_ptr) : "memory")
#define CP_COMMIT() asm volatile("cp.async.commit_group;" ::: "memory")
#define CP_WAIT(n)  asm volatile("cp.async.wait_group %0;" :: "n"(n) : "memory")

// ---------------------------------------------------------------------------
// Mask dtype detector
// ---------------------------------------------------------------------------
__global__ void detect_mask_kernel(const unsigned char* __restrict__ mb) {
    __shared__ int any;
    if (threadIdx.x == 0) any = 0;
    __syncthreads();
    for (int i = threadIdx.x; i < 4096; i += blockDim.x) {
        if ((i & 3) && mb[i]) atomicOr(&any, 1);
    }
    __syncthreads();
    if (threadIdx.x == 0) g_mask_is_i32 = any ? 0 : 1;
}

// ---------------------------------------------------------------------------
// fp32 -> fp16 elementwise convert (4 per thread)
// ---------------------------------------------------------------------------
__global__ void convert_h_kernel(const float* __restrict__ S, __half* __restrict__ D,
                                 long long n4) {
    const long long idx = (long long)blockIdx.x * blockDim.x + threadIdx.x;
    if (idx >= n4) return;
    const long long i = idx * 4;
    const float4 v = *(const float4*)(S + i);
    *(__half2*)(D + i)     = __floats2half2_rn(v.x, v.y);
    *(__half2*)(D + i + 2) = __floats2half2_rn(v.z, v.w);
}

// ---------------------------------------------------------------------------
// Tiled transpose with fp16 output: src fp32 [R][C] -> dst half [C][R]
// ---------------------------------------------------------------------------
__global__ void transpose_h_kernel(const float* __restrict__ S, __half* __restrict__ D,
                                   int R, int C, long long sS, long long sD) {
    __shared__ float tile[32][33];
    const float* s = S + (long long)blockIdx.z * sS;
    __half* d = D + (long long)blockIdx.z * sD;
    const int x = blockIdx.x * 32 + threadIdx.x;
    const int y0 = blockIdx.y * 32;
    #pragma unroll
    for (int i = threadIdx.y; i < 32; i += 8)
        tile[i][threadIdx.x] = s[(long long)(y0 + i) * C + x];
    __syncthreads();
    const int xo = blockIdx.y * 32 + threadIdx.x;
    const int yo0 = blockIdx.x * 32;
    #pragma unroll
    for (int i = threadIdx.y; i < 32; i += 8)
        d[(long long)(yo0 + i) * R + xo] = __float2half_rn(tile[threadIdx.x][i]);
}

// ===========================================================================
// Multistage fp16 mma.sync NT GEMM (fp32 accumulate):
//   C[m,n] = epilogue( sum_k A[m,k] * B[n,k] )
// A: half [M][K], B: half [N][K]. Block tile 128x128, 256 thr, 8 warps
// (4m x 2n), warp tile 32x64. K-slab 64, 3-stage cp.async.
// EPI: 0 = +bias+relu (half out), 1 = +bias (half out),
//      2 = QK mask/scale (float out), 3 = plain (float out)
// ===========================================================================
template<int EPI>
__global__ void __launch_bounds__(256, 2) gemm_h(
    const __half* __restrict__ Ag, const __half* __restrict__ Bg,
    const float* __restrict__ bias, void* __restrict__ Cg,
    int K, int ldc, long long sA, long long sB, long long sC,
    const void* __restrict__ maskp)
{
    extern __shared__ __half smh[];
    const uint32_t sbase = smem_u32(smh);
    const int tid  = threadIdx.x;
    const int warp = tid >> 5;
    const int lane = tid & 31;
    const int wm = (warp >> 1) * 32;
    const int wn = (warp & 1) * 64;

    const __half* A = Ag + (long long)blockIdx.z * sA;
    const __half* B = Bg + (long long)blockIdx.z * sB;
    const int bm = blockIdx.y * 128;
    const int bn = blockIdx.x * 128;

    // loader: 128 rows x 64 halves per tile = 1024 16B-chunks; A+B = 2048;
    // 8 chunks/thread (4 A + 4 B).
    auto load_stage = [&](int t, int buf) {
        const __half* Abase = A + (long long)bm * K + t * TKS;
        const __half* Bbase = B + (long long)bn * K + t * TKS;
        const uint32_t s0 = sbase + (uint32_t)(buf * STAGE_HALVES) * 2u;
        #pragma unroll
        for (int i = 0; i < 4; i++) {
            const int c = tid + i * 256;
            const int m = c >> 3, kc = c & 7;
            CP_ASYNC16(s0 + (uint32_t)(m * RS + kc * 8) * 2u,
                       Abase + (long long)m * K + kc * 8);
            CP_ASYNC16(s0 + (uint32_t)(TILE_HALVES + m * RS + kc * 8) * 2u,
                       Bbase + (long long)m * K + kc * 8);
        }
    };

    float4 acc[2][8];
    #pragma unroll
    for (int i = 0; i < 2; i++)
        #pragma unroll
        for (int j = 0; j < 8; j++) acc[i][j] = make_float4(0.f, 0.f, 0.f, 0.f);

    const int T = K / TKS;

    load_stage(0, 0); CP_COMMIT();
    load_stage(1, 1); CP_COMMIT();

    for (int t = 0; t < T; t++) {
        const int buf = t % NSTAGE;
        CP_WAIT(1);                 // stage t resident
        __syncthreads();            // also orders compute(t-1) before buffer reuse
        if (t + 2 < T) load_stage(t + 2, (t + 2) % NSTAGE);
        CP_COMMIT();                // uniform group accounting

        const __half* As = smh + buf * STAGE_HALVES;
        const __half* Bs = As + TILE_HALVES;

        #pragma unroll
        for (int ks = 0; ks < 4; ks++) {
            const int ck = ks * 16 + (lane & 3) * 2;
            uint32_t af[2][4];
            #pragma unroll
            for (int i = 0; i < 2; i++) {
                const int r = wm + i * 16 + (lane >> 2);
                af[i][0] = *(const uint32_t*)(As + r * RS + ck);
                af[i][1] = *(const uint32_t*)(As + (r + 8) * RS + ck);
                af[i][2] = *(const uint32_t*)(As + r * RS + ck + 8);
                af[i][3] = *(const uint32_t*)(As + (r + 8) * RS + ck + 8);
            }
            #pragma unroll
            for (int j = 0; j < 8; j++) {
                const int n = wn + j * 8 + (lane >> 2);
                const uint32_t b0 = *(const uint32_t*)(Bs + n * RS + ck);
                const uint32_t b1 = *(const uint32_t*)(Bs + n * RS + ck + 8);
                mma_f16(acc[0][j], af[0][0], af[0][1], af[0][2], af[0][3], b0, b1);
                mma_f16(acc[1][j], af[1][0], af[1][1], af[1][2], af[1][3], b0, b1);
            }
        }
        // no trailing sync: top-of-loop barrier provides the ordering
    }

    // Epilogue: c0,c1 -> (r, c..c+1); c2,c3 -> (r+8, c..c+1)
    const int is_i32 = (EPI == 2) ? g_mask_is_i32 : 0;
    #pragma unroll
    for (int i = 0; i < 2; i++) {
        const int r0 = bm + wm + i * 16 + (lane >> 2);
        const int r1 = r0 + 8;
        #pragma unroll
        for (int j = 0; j < 8; j++) {
            const int c = bn + wn + j * 8 + (lane & 3) * 2;
            float2 v0 = make_float2(acc[i][j].x, acc[i][j].y);
            float2 v1 = make_float2(acc[i][j].z, acc[i][j].w);
            if (EPI == 0 || EPI == 1) {
                const float2 b = *(const float2*)(bias + c);
                v0.x += b.x; v0.y += b.y;
                v1.x += b.x; v1.y += b.y;
                if (EPI == 0) {
                    v0.x = fmaxf(v0.x, 0.f); v0.y = fmaxf(v0.y, 0.f);
                    v1.x = fmaxf(v1.x, 0.f); v1.y = fmaxf(v1.y, 0.f);
                }
                __half* C = (__half*)Cg + (long long)blockIdx.z * sC;
                *(__half2*)(C + (long long)r0 * ldc + c) = __floats2half2_rn(v0.x, v0.y);
                *(__half2*)(C + (long long)r1 * ldc + c) = __floats2half2_rn(v1.x, v1.y);
            } else {
                if (EPI == 2) {
                    const long long base = (long long)blockIdx.z * SS * SS;
                    const long long i00 = base + (long long)r0 * SS + c;
                    const long long i10 = base + (long long)r1 * SS + c;
                    bool m00, m01, m10, m11;
                    if (is_i32) {
                        const int* mi = (const int*)maskp;
                        m00 = mi[i00] != 0; m01 = mi[i00 + 1] != 0;
                        m10 = mi[i10] != 0; m11 = mi[i10 + 1] != 0;
                    } else {
                        const unsigned char* mu = (const unsigned char*)maskp;
                        m00 = mu[i00] != 0; m01 = mu[i00 + 1] != 0;
                        m10 = mu[i10] != 0; m11 = mu[i10 + 1] != 0;
                    }
                    v0.x = m00 ? -1e16f : v0.x * INV_T;
                    v0.y = m01 ? -1e16f : v0.y * INV_T;
                    v1.x = m10 ? -1e16f : v1.x * INV_T;
                    v1.y = m11 ? -1e16f : v1.y * INV_T;
                }
                float* C = (float*)Cg + (long long)blockIdx.z * sC;
                *(float2*)(C + (long long)r0 * ldc + c) = v0;
                *(float2*)(C + (long long)r1 * ldc + c) = v1;
            }
        }
    }
}

// ---------------------------------------------------------------------------
// Block reductions
// ---------------------------------------------------------------------------
__device__ __forceinline__ float blockReduceSum(float v, float* sh) {
    #pragma unroll
    for (int o = 16; o > 0; o >>= 1) v += __shfl_xor_sync(0xffffffffu, v, o);
    __syncthreads();
    if ((threadIdx.x & 31) == 0) sh[threadIdx.x >> 5] = v;
    __syncthreads();
    if (threadIdx.x < 32) {
        v = (threadIdx.x < (blockDim.x >> 5)) ? sh[threadIdx.x] : 0.0f;
        #pragma unroll
        for (int o = 16; o > 0; o >>= 1) v += __shfl_xor_sync(0xffffffffu, v, o);
        if (threadIdx.x == 0) sh[0] = v;
    }
    __syncthreads();
    return sh[0];
}

__device__ __forceinline__ float blockReduceMax(float v, float* sh) {
    #pragma unroll
    for (int o = 16; o > 0; o >>= 1) v = fmaxf(v, __shfl_xor_sync(0xffffffffu, v, o));
    __syncthreads();
    if ((threadIdx.x & 31) == 0) sh[threadIdx.x >> 5] = v;
    __syncthreads();
    if (threadIdx.x < 32) {
        v = (threadIdx.x < (blockDim.x >> 5)) ? sh[threadIdx.x] : -3.0e38f;
        #pragma unroll
        for (int o = 16; o > 0; o >>= 1) v = fmaxf(v, __shfl_xor_sync(0xffffffffu, v, o));
        if (threadIdx.x == 0) sh[0] = v;
    }
    __syncthreads();
    return sh[0];
}

// ---------------------------------------------------------------------------
// LayerNorm + ReLU: half in, half out (stats in fp32)
// ---------------------------------------------------------------------------
__global__ void ln_relu_h_kernel(const __half* __restrict__ X,
                                 const float* __restrict__ g,
                                 const float* __restrict__ beta,
                                 __half* __restrict__ Y)
{
    __shared__ float sh[32];
    const long long row = blockIdx.x;
    const __half* x = X + row * DD;
    const int t = threadIdx.x;

    const __half2 h0 = *(const __half2*)(x + t * 4);
    const __half2 h1 = *(const __half2*)(x + t * 4 + 2);
    const float2 f0 = __half22float2(h0);
    const float2 f1 = __half22float2(h1);
    float s  = f0.x + f0.y + f1.x + f1.y;
    float sq = f0.x * f0.x + f0.y * f0.y + f1.x * f1.x + f1.y * f1.y;
    s  = blockReduceSum(s, sh);
    sq = blockReduceSum(sq, sh);
    const float mu  = s * (1.0f / DD);
    const float var = sq * (1.0f / DD) - mu * mu;
    const float r = rsqrtf(var + LN_EPS);

    const float4 gv = *(const float4*)(g + t * 4);
    const float4 bv = *(const float4*)(beta + t * 4);
    float y0 = fmaxf((f0.x - mu) * r * gv.x + bv.x, 0.0f);
    float y1 = fmaxf((f0.y - mu) * r * gv.y + bv.y, 0.0f);
    float y2 = fmaxf((f1.x - mu) * r * gv.z + bv.z, 0.0f);
    float y3 = fmaxf((f1.y - mu) * r * gv.w + bv.w, 0.0f);
    *(__half2*)(Y + row * DD + t * 4)     = __floats2half2_rn(y0, y1);
    *(__half2*)(Y + row * DD + t * 4 + 2) = __floats2half2_rn(y2, y3);
}

// ---------------------------------------------------------------------------
// Negated softmax over rows of 2048, in place (fp32) + half mirror for PV.
// ---------------------------------------------------------------------------
__global__ void softmax_neg_kernel(float* __restrict__ P, __half* __restrict__ PH) {
    __shared__ float sh[32];
    float* p = P + (long long)blockIdx.x * SS;
    __half* ph = PH + (long long)blockIdx.x * SS;
    const int t = threadIdx.x;

    float4 x0 = *(float4*)(p + t * 8);
    float4 x1 = *(float4*)(p + t * 8 + 4);
    float mx = fmaxf(fmaxf(fmaxf(x0.x, x0.y), fmaxf(x0.z, x0.w)),
                     fmaxf(fmaxf(x1.x, x1.y), fmaxf(x1.z, x1.w)));
    mx = blockReduceMax(mx, sh);

    float e[8];
    e[0] = __expf(x0.x - mx); e[1] = __expf(x0.y - mx);
    e[2] = __expf(x0.z - mx); e[3] = __expf(x0.w - mx);
    e[4] = __expf(x1.x - mx); e[5] = __expf(x1.y - mx);
    e[6] = __expf(x1.z - mx); e[7] = __expf(x1.w - mx);
    float s = e[0] + e[1] + e[2] + e[3] + e[4] + e[5] + e[6] + e[7];
    s = blockReduceSum(s, sh);
    const float inv = -1.0f / s;

    x0.x = e[0] * inv; x0.y = e[1] * inv; x0.z = e[2] * inv; x0.w = e[3] * inv;
    x1.x = e[4] * inv; x1.y = e[5] * inv; x1.z = e[6] * inv; x1.w = e[7] * inv;
    *(float4*)(p + t * 8)     = x0;
    *(float4*)(p + t * 8 + 4) = x1;
    *(__half2*)(ph + t * 8)     = __floats2half2_rn(x0.x, x0.y);
    *(__half2*)(ph + t * 8 + 2) = __floats2half2_rn(x0.z, x0.w);
    *(__half2*)(ph + t * 8 + 4) = __floats2half2_rn(x1.x, x1.y);
    *(__half2*)(ph + t * 8 + 6) = __floats2half2_rn(x1.z, x1.w);
}

// ---------------------------------------------------------------------------
// Launch
// ---------------------------------------------------------------------------
extern "C" void kernel_launch(void* const* d_in, const int* in_sizes, int n_in,
                              void* d_out, int out_size)
{
    const float* q   = (const float*)d_in[0];
    const float* k   = (const float*)d_in[1];
    const float* v   = (const float*)d_in[2];
    const void*  mask = d_in[3];
    const float* qw1 = (const float*)d_in[4];
    const float* qw2 = (const float*)d_in[5];
    const float* qw3 = (const float*)d_in[6];
    const float* kw1 = (const float*)d_in[7];
    const float* kw2 = (const float*)d_in[8];
    const float* kw3 = (const float*)d_in[9];
    const float* qb1 = (const float*)d_in[10];
    const float* qb2 = (const float*)d_in[11];
    const float* qb3 = (const float*)d_in[12];
    const float* kb1 = (const float*)d_in[13];
    const float* kb2 = (const float*)d_in[14];
    const float* kb3 = (const float*)d_in[15];
    const float* q_ln_b = (const float*)d_in[16];
    const float* k_ln_b = (const float*)d_in[17];
    const float* q_ln_g = (const float*)d_in[18];
    const float* k_ln_g = (const float*)d_in[19];

    float* out  = (float*)d_out;                              // [B,S,D]
    float* attn = out + (long long)BB * SS * DD;              // [B,S,S]

    __half *qh, *kh, *t1, *t2, *dq, *dk, *wt, *vt, *ah;
    cudaGetSymbolAddress((void**)&qh, g_qh);
    cudaGetSymbolAddress((void**)&kh, g_kh);
    cudaGetSymbolAddress((void**)&t1, g_t1);
    cudaGetSymbolAddress((void**)&t2, g_t2);
    cudaGetSymbolAddress((void**)&dq, g_dq);
    cudaGetSymbolAddress((void**)&dk, g_dk);
    cudaGetSymbolAddress((void**)&wt, g_wt);
    cudaGetSymbolAddress((void**)&vt, g_vt);
    cudaGetSymbolAddress((void**)&ah, g_ah);

    const size_t shm = GEMM_SMEM_BYTES;
    cudaFuncSetAttribute(gemm_h<0>, cudaFuncAttributeMaxDynamicSharedMemorySize, shm);
    cudaFuncSetAttribute(gemm_h<1>, cudaFuncAttributeMaxDynamicSharedMemorySize, shm);
    cudaFuncSetAttribute(gemm_h<2>, cudaFuncAttributeMaxDynamicSharedMemorySize, shm);
    cudaFuncSetAttribute(gemm_h<3>, cudaFuncAttributeMaxDynamicSharedMemorySize, shm);

    detect_mask_kernel<<<1, 256>>>((const unsigned char*)mask);

    // fp32 -> fp16 inputs
    const long long n4 = (long long)MFULL * DD / 4;
    convert_h_kernel<<<(int)((n4 + 255) / 256), 256>>>(q, qh, n4);
    convert_h_kernel<<<(int)((n4 + 255) / 256), 256>>>(k, kh, n4);

    // Weights W[k][n] -> half Wt[n][k]
    const float* ws[6] = {qw1, qw2, qw3, kw1, kw2, kw3};
    for (int i = 0; i < 6; i++)
        transpose_h_kernel<<<dim3(16, 16, 1), dim3(32, 8)>>>(
            ws[i], wt + (long long)i * DD * DD, DD, DD, 0, 0);
    __half* wtq1 = wt + 0LL * DD * DD; __half* wtq2 = wt + 1LL * DD * DD;
    __half* wtq3 = wt + 2LL * DD * DD; __half* wtk1 = wt + 3LL * DD * DD;
    __half* wtk2 = wt + 4LL * DD * DD; __half* wtk3 = wt + 5LL * DD * DD;

    // V[b][t][d] -> half Vt[b][d][t]
    transpose_h_kernel<<<dim3(DD / 32, SS / 32, BB), dim3(32, 8)>>>(
        v, vt, SS, DD, (long long)SS * DD, (long long)DD * SS);

    const dim3 gMLP(DD / 128, MFULL / 128, 1);    // (4, 128, 1)

    // ---- deep_q ----
    gemm_h<0><<<gMLP, 256, shm>>>(qh, wtq1, qb1, t1, DD, DD, 0, 0, 0, nullptr);
    gemm_h<1><<<gMLP, 256, shm>>>(t1, wtq2, qb2, t2, DD, DD, 0, 0, 0, nullptr);
    ln_relu_h_kernel<<<MFULL, 128>>>(t2, q_ln_g, q_ln_b, t1);
    gemm_h<1><<<gMLP, 256, shm>>>(t1, wtq3, qb3, dq, DD, DD, 0, 0, 0, nullptr);

    // ---- deep_k ----
    gemm_h<0><<<gMLP, 256, shm>>>(kh, wtk1, kb1, t1, DD, DD, 0, 0, 0, nullptr);
    gemm_h<1><<<gMLP, 256, shm>>>(t1, wtk2, kb2, t2, DD, DD, 0, 0, 0, nullptr);
    ln_relu_h_kernel<<<MFULL, 128>>>(t2, k_ln_g, k_ln_b, t1);
    gemm_h<1><<<gMLP, 256, shm>>>(t1, wtk3, kb3, dk, DD, DD, 0, 0, 0, nullptr);

    // ---- attention ----
    gemm_h<2><<<dim3(SS / 128, SS / 128, BB), 256, shm>>>(
        dq, dk, nullptr, attn, DD, SS,
        (long long)SS * DD, (long long)SS * DD, (long long)SS * SS, mask);
    softmax_neg_kernel<<<MFULL, 256>>>(attn, ah);
    gemm_h<3><<<dim3(DD / 128, SS / 128, BB), 256, shm>>>(
        ah, vt, nullptr, out, SS, DD,
        (long long)SS * SS, (long long)DD * SS, (long long)SS * DD, nullptr);
}